// round 11
// baseline (speedup 1.0000x reference)
#include <cuda_runtime.h>
#include <math.h>

// Problem constants: N=100000, L=48, E=1600000, ED=17, H=48
#define NN 100000
#define LL 48
#define EDD 17
#define EEMAX 1600000
#define CAP (1<<18)
#define NCAP (1<<16)
#define NBW 3136            // ceil(100000/32)=3125 padded to x4
#define GRID 148
#define TPB 1024
#define FULL 0xffffffffu

__device__ float g_x[NN*LL];
__device__ float g_v[NN*LL];
__device__ float g_agg[NN*LL];          // invariant: all-zero between runs
__device__ float g_wbase[EEMAX];
__device__ __align__(16) unsigned int g_flag1b[NBW];
__device__ __align__(16) unsigned int g_flag2b[NBW];
__device__ int g_list1[CAP];
__device__ int g_list2[CAP];
__device__ int g_list3[CAP];
__device__ int g_nlist1[NCAP];
__device__ int g_nlist2[NCAP];
__device__ int g_cnt[4];
__device__ int g_ncnt[4];
__device__ volatile int g_bar[8];

__device__ __forceinline__ float geluf(float x) {
    return 0.5f * x * (1.0f + erff(x * 0.70710678118654752f));
}
__device__ __forceinline__ float sigm(float x) {
    return 1.0f / (1.0f + expf(-x));
}
__device__ __forceinline__ bool mark_bit(unsigned int* fw, int s) {
    unsigned int b = 1u << (s & 31);
    return (atomicOr(&fw[s >> 5], b) & b) == 0u;
}

// barrier: arrival = 1 atomic RMW; poll = volatile plain load (no RMW storm)
__device__ __forceinline__ void gbar_wait(int idx) {
    __syncthreads();
    if (threadIdx.x == 0) {
        __threadfence();
        atomicAdd((int*)&g_bar[idx], 1);
        while (g_bar[idx] < GRID) __nanosleep(32);
        __threadfence();
    }
    __syncthreads();
}
__device__ __forceinline__ void gbar_arrive(int idx) {
    __syncthreads();
    if (threadIdx.x == 0) {
        __threadfence();
        atomicAdd((int*)&g_bar[idx], 1);
    }
}

// full-warp edge MLP: returns w_base on ALL lanes
__device__ __forceinline__ float edge_mlp(int eid, int lane, bool lo,
        const float* __restrict__ ea_all,
        const float* __restrict__ W1, const float* __restrict__ b1,
        const float* __restrict__ W2, const float* __restrict__ b2,
        const float* __restrict__ Wg, const float* __restrict__ bg,
        const float* __restrict__ Ww, float bw0) {
    const float* ea = ea_all + (long long)eid * EDD;

    float a  = b1[lane];
    float a2 = lo ? b1[lane + 32] : 0.f;
    #pragma unroll
    for (int k = 0; k < EDD; k++) {
        float ev = __ldg(&ea[k]);
        a = fmaf(ev, W1[k * 48 + lane], a);
        if (lo) a2 = fmaf(ev, W1[k * 48 + lane + 32], a2);
    }
    a = geluf(a); a2 = geluf(a2);

    float c  = b2[lane];
    float c2 = lo ? b2[lane + 32] : 0.f;
    #pragma unroll
    for (int k = 0; k < 48; k++) {
        float hk = (k < 32) ? __shfl_sync(FULL, a, k)
                            : __shfl_sync(FULL, a2, k - 32);
        c = fmaf(hk, W2[k * 48 + lane], c);
        if (lo) c2 = fmaf(hk, W2[k * 48 + lane + 32], c2);
    }
    c = fmaxf(c, 0.f); c2 = fmaxf(c2, 0.f);

    float d1 = bg[lane];
    float d2 = lo ? bg[lane + 32] : 0.f;
    #pragma unroll
    for (int k = 0; k < 48; k++) {
        float hk = (k < 32) ? __shfl_sync(FULL, c, k)
                            : __shfl_sync(FULL, c2, k - 32);
        d1 = fmaf(hk, Wg[k * 48 + lane], d1);
        if (lo) d2 = fmaf(hk, Wg[k * 48 + lane + 32], d2);
    }
    d1 = geluf(d1); d2 = geluf(d2);

    float p = d1 * Ww[lane] + (lo ? d2 * Ww[lane + 32] : 0.f);
    #pragma unroll
    for (int off = 16; off; off >>= 1) p += __shfl_xor_sync(FULL, p, off);
    return p + bw0;
}

__global__ void __launch_bounds__(TPB)
k_main(const int* __restrict__ src, const int* __restrict__ dst, int e,
       const float* __restrict__ nodes, const float* __restrict__ valid,
       const float* __restrict__ ea_all,
       const float* __restrict__ W1, const float* __restrict__ b1,
       const float* __restrict__ W2, const float* __restrict__ b2,
       const float* __restrict__ Wg, const float* __restrict__ bg,
       const float* __restrict__ Ww, const float* __restrict__ bw,
       const float* __restrict__ Wf, const float* __restrict__ bf,
       float* __restrict__ out) {
    __shared__ __align__(16) unsigned int sflag[NBW];
    const int tid  = threadIdx.x;
    const int lane = tid & 31;
    const bool lo  = (lane < 16);
    const int gtid = blockIdx.x * TPB + tid;
    const int gthreads = GRID * TPB;
    const long long stride8 = (long long)gthreads * 8;

    // seed node 0 into both frontiers (flags guaranteed zero at entry)
    if (gtid == 0) {
        if (mark_bit(g_flag2b, 0)) {
            int q = atomicAdd(&g_ncnt[2], 1);
            if (q < NCAP) g_nlist2[q] = 0;
        }
        if (mark_bit(g_flag1b, 0)) {
            int q = atomicAdd(&g_ncnt[1], 1);
            if (q < NCAP) g_nlist1[q] = 0;
        }
    }

    // ---------------- Phase 1: scan3 (dst==0) ----------------
    for (long long base = (long long)gtid * 8;; base += stride8) {
        if (!__ballot_sync(FULL, base < e)) break;
        int d[8];
        #pragma unroll
        for (int t = 0; t < 8; t++) d[t] = -1;
        if (base < e) {
            if (base + 8 <= e) {
                int4 a = __ldg((const int4*)(dst + base));
                int4 b = __ldg((const int4*)(dst + base + 4));
                d[0]=a.x; d[1]=a.y; d[2]=a.z; d[3]=a.w;
                d[4]=b.x; d[5]=b.y; d[6]=b.z; d[7]=b.w;
            } else {
                #pragma unroll
                for (int t = 0; t < 8; t++) if (base + t < e) d[t] = dst[base + t];
            }
        }
        int mymask = 0;
        #pragma unroll
        for (int t = 0; t < 8; t++) if (d[t] == 0) mymask |= 1 << t;
        if (__ballot_sync(FULL, mymask != 0)) {
            #pragma unroll 1
            for (int t = 0; t < 8; t++) {
                bool pred = (mymask >> t) & 1;
                unsigned int m = __ballot_sync(FULL, pred);
                if (!m) continue;
                int leader = __ffs(m) - 1;
                int pos0 = 0;
                if (lane == leader) pos0 = atomicAdd(&g_cnt[3], __popc(m));
                pos0 = __shfl_sync(FULL, pos0, leader);
                if (pred) {
                    int p = pos0 + __popc(m & ((1u << lane) - 1));
                    int i = (int)(base + t);
                    if (p < CAP) g_list3[p] = i;
                    int s = __ldg(&src[i]);
                    if (mark_bit(g_flag2b, s)) {
                        int q = atomicAdd(&g_ncnt[2], 1);
                        if (q < NCAP) g_nlist2[q] = s;
                    }
                    if (mark_bit(g_flag1b, s)) {
                        int q = atomicAdd(&g_ncnt[1], 1);
                        if (q < NCAP) g_nlist1[q] = s;
                    }
                }
            }
        }
    }
    gbar_wait(0);

    // ---------------- Phase 2: stage flag2, scan2 ----------------
    {
        const uint4* gs = (const uint4*)g_flag2b;
        uint4* sd = (uint4*)sflag;
        for (int i = tid; i < NBW / 4; i += TPB) sd[i] = __ldcg(&gs[i]);
    }
    __syncthreads();
    for (long long base = (long long)gtid * 8;; base += stride8) {
        if (!__ballot_sync(FULL, base < e)) break;
        int d[8];
        #pragma unroll
        for (int t = 0; t < 8; t++) d[t] = -1;
        if (base < e) {
            if (base + 8 <= e) {
                int4 a = __ldg((const int4*)(dst + base));      // L1-hot after P1
                int4 b = __ldg((const int4*)(dst + base + 4));
                d[0]=a.x; d[1]=a.y; d[2]=a.z; d[3]=a.w;
                d[4]=b.x; d[5]=b.y; d[6]=b.z; d[7]=b.w;
            } else {
                #pragma unroll
                for (int t = 0; t < 8; t++) if (base + t < e) d[t] = dst[base + t];
            }
        }
        int mymask = 0;
        #pragma unroll
        for (int t = 0; t < 8; t++)
            if (d[t] >= 0 && ((sflag[d[t] >> 5] >> (d[t] & 31)) & 1u)) mymask |= 1 << t;
        if (__ballot_sync(FULL, mymask != 0)) {
            #pragma unroll 1
            for (int t = 0; t < 8; t++) {
                bool pred = (mymask >> t) & 1;
                unsigned int m = __ballot_sync(FULL, pred);
                if (!m) continue;
                int leader = __ffs(m) - 1;
                int pos0 = 0;
                if (lane == leader) pos0 = atomicAdd(&g_cnt[2], __popc(m));
                pos0 = __shfl_sync(FULL, pos0, leader);
                if (pred) {
                    int p = pos0 + __popc(m & ((1u << lane) - 1));
                    int i = (int)(base + t);
                    if (p < CAP) g_list2[p] = i;
                    int s = __ldg(&src[i]);
                    if (mark_bit(g_flag1b, s)) {
                        int q = atomicAdd(&g_ncnt[1], 1);
                        if (q < NCAP) g_nlist1[q] = s;
                    }
                }
            }
        }
    }
    gbar_wait(1);

    // ---------------- Phase 3: stage flag1, scan1 -> list1 ----------------
    {
        const uint4* gs = (const uint4*)g_flag1b;
        uint4* sd = (uint4*)sflag;
        for (int i = tid; i < NBW / 4; i += TPB) sd[i] = __ldcg(&gs[i]);
    }
    __syncthreads();
    for (long long base = (long long)gtid * 8;; base += stride8) {
        if (!__ballot_sync(FULL, base < e)) break;
        int d[8];
        #pragma unroll
        for (int t = 0; t < 8; t++) d[t] = -1;
        if (base < e) {
            if (base + 8 <= e) {
                int4 a = __ldg((const int4*)(dst + base));
                int4 b = __ldg((const int4*)(dst + base + 4));
                d[0]=a.x; d[1]=a.y; d[2]=a.z; d[3]=a.w;
                d[4]=b.x; d[5]=b.y; d[6]=b.z; d[7]=b.w;
            } else {
                #pragma unroll
                for (int t = 0; t < 8; t++) if (base + t < e) d[t] = dst[base + t];
            }
        }
        int mymask = 0;
        #pragma unroll
        for (int t = 0; t < 8; t++)
            if (d[t] >= 0 && ((sflag[d[t] >> 5] >> (d[t] & 31)) & 1u)) mymask |= 1 << t;
        if (__ballot_sync(FULL, mymask != 0)) {
            #pragma unroll 1
            for (int t = 0; t < 8; t++) {
                bool pred = (mymask >> t) & 1;
                unsigned int m = __ballot_sync(FULL, pred);
                if (!m) continue;
                int leader = __ffs(m) - 1;
                int pos0 = 0;
                if (lane == leader) pos0 = atomicAdd(&g_cnt[1], __popc(m));
                pos0 = __shfl_sync(FULL, pos0, leader);
                if (pred) {
                    int p = pos0 + __popc(m & ((1u << lane) - 1));
                    if (p < CAP) g_list1[p] = (int)(base + t);
                }
            }
        }
    }
    gbar_wait(2);

    // ---------------- Phase 4: balanced wbase + agg1 over list1 ----------------
    {
        int gwarp = gtid >> 5;
        int nwarp = gthreads >> 5;
        int cnt = min(__ldcg(&g_cnt[1]), CAP);
        float bw0 = __ldg(bw);

        for (int it = gwarp; it < cnt; it += nwarp) {
            int eid = __ldcg(&g_list1[it]);
            float wb = edge_mlp(eid, lane, lo, ea_all, W1, b1, W2, b2,
                                Wg, bg, Ww, bw0);
            if (lane == 0) g_wbase[eid] = wb;

            int s = __ldg(&src[eid]);
            int dn = __ldg(&dst[eid]);
            long long sb = (long long)s * LL;
            float v0 = __ldg(&valid[sb + lane]);
            float v1 = lo ? __ldg(&valid[sb + lane + 32]) : 0.f;
            float x0 = __ldg(&nodes[sb + lane]) * v0;
            float x1 = lo ? __ldg(&nodes[sb + lane + 32]) * v1 : 0.f;
            float sv = v0 + v1;
            #pragma unroll
            for (int off = 16; off; off >>= 1) sv += __shfl_xor_sync(FULL, sv, off);
            float sg = sigm((sv * (1.0f / 48.0f)) * wb);
            float* ad = g_agg + (long long)dn * LL;
            atomicAdd(&ad[lane], x0 * sg);
            if (lo) atomicAdd(&ad[lane + 32], x1 * sg);
        }
    }
    gbar_wait(3);

    // ---------------- Phase 5: grid-wide upd1 over nlist1 (restores agg=0) ----
    {
        float wf0 = __ldg(&Wf[0]), wf1 = __ldg(&Wf[1]), wf2 = __ldg(&Wf[2]);
        float b0 = __ldg(bf);
        int total = min(__ldcg(&g_ncnt[1]), NCAP) * LL;
        for (int q = gtid; q < total; q += gthreads) {
            int u = __ldcg(&g_nlist1[q / LL]);
            int l = q % LL;
            long long i = (long long)u * LL + l;
            float vo = __ldg(&valid[i]);
            float orig = __ldg(&nodes[i]) * vo;
            float xo = orig;
            float nh = __ldcg(&g_agg[i]);
            float nv = 1.0f - vo;
            float mm = sigm(nh * wf0 + xo * wf1 + nv * wf2 + b0);
            float xn = (1.0f - mm) * xo + nv * mm * nh;
            float vn = (l != 0 && (orig != xn || vo > 0.0f)) ? 1.0f : 0.0f;
            g_x[i] = xn;
            g_v[i] = vn;
            g_agg[i] = 0.f;
        }
    }
    gbar_arrive(4);

    // ---------------- Epilogue ----------------
    if (blockIdx.x != 0) {
        // parallel flag reset by exiting blocks (flags unused after P3 staging)
        int per = (NBW + GRID - 2) / (GRID - 1);
        int s0 = (blockIdx.x - 1) * per;
        int s1 = min(s0 + per, NBW);
        for (int i = s0 + tid; i < s1; i += TPB) {
            g_flag1b[i] = 0u;
            g_flag2b[i] = 0u;
        }
        return;
    }
    if (tid == 0) {
        while (g_bar[4] < GRID) __nanosleep(32);
        __threadfence();
    }
    __syncthreads();

    // Block 0: tail levels 2 and 3 (tiny), then reset counters/barriers
    float wf0 = __ldg(&Wf[0]), wf1 = __ldg(&Wf[1]), wf2 = __ldg(&Wf[2]);
    float b0 = __ldg(bf);

    #pragma unroll 1
    for (int level = 2; level <= 3; level++) {
        const int* list = (level == 2) ? g_list2 : g_list3;
        int cnt = min(__ldcg(&g_cnt[level]), CAP);
        int warp = tid >> 5;
        for (int it = warp; it < cnt; it += (TPB >> 5)) {
            int eid = __ldcg(&list[it]);
            int s = __ldg(&src[eid]);
            int dn = __ldg(&dst[eid]);
            long long sb = (long long)s * LL;
            float v0 = g_v[sb + lane];
            float v1 = lo ? g_v[sb + lane + 32] : 0.f;
            float x0 = g_x[sb + lane];
            float x1 = lo ? g_x[sb + lane + 32] : 0.f;
            float sv = v0 + v1;
            #pragma unroll
            for (int off = 16; off; off >>= 1) sv += __shfl_xor_sync(FULL, sv, off);
            float sg = sigm((sv * (1.0f / 48.0f)) * __ldcg(&g_wbase[eid]));
            float* ad = g_agg + (long long)dn * LL;
            atomicAdd(&ad[lane], x0 * sg);
            if (lo) atomicAdd(&ad[lane + 32], x1 * sg);
        }
        __syncthreads();

        int ncnt = (level == 2) ? min(__ldcg(&g_ncnt[2]), NCAP) : 1;
        int total = ncnt * LL;
        for (int q = tid; q < total; q += TPB) {
            int u = (level == 2) ? __ldcg(&g_nlist2[q / LL]) : 0;
            int l = q % LL;
            long long i = (long long)u * LL + l;
            float vv = __ldg(&valid[i]);
            float orig = __ldg(&nodes[i]) * vv;
            float xo = g_x[i];
            float vo = g_v[i];
            float nh = __ldcg(&g_agg[i]);
            float nv = 1.0f - vo;
            float mm = sigm(nh * wf0 + xo * wf1 + nv * wf2 + b0);
            float xn = (1.0f - mm) * xo + nv * mm * nh;
            float vn = (l != 0 && (orig != xn || vo > 0.0f)) ? 1.0f : 0.0f;
            g_x[i] = xn;
            g_v[i] = vn;
            g_agg[i] = 0.f;
            if (level == 3) out[l] = xn;
        }
        __syncthreads();
    }

    // reset counters + barriers for next replay
    if (tid < 4) {
        g_cnt[tid] = 0;
        g_ncnt[tid] = 0;
    }
    if (tid >= 4 && tid < 12) ((int*)g_bar)[tid - 4] = 0;
}

extern "C" void kernel_launch(void* const* d_in, const int* in_sizes, int n_in,
                              void* d_out, int out_size) {
    const float* nodes     = (const float*)d_in[0];
    const int*   ei        = (const int*)d_in[1];
    const float* edge_attr = (const float*)d_in[2];
    const float* valid     = (const float*)d_in[3];
    const float* W1 = (const float*)d_in[6];
    const float* b1 = (const float*)d_in[7];
    const float* W2 = (const float*)d_in[8];
    const float* b2 = (const float*)d_in[9];
    const float* Wg = (const float*)d_in[10];
    const float* bg = (const float*)d_in[11];
    const float* Ww = (const float*)d_in[12];
    const float* bw = (const float*)d_in[13];
    const float* Wf = (const float*)d_in[14];
    const float* bf = (const float*)d_in[15];

    int e = in_sizes[1] / 2;
    const int* src = ei;
    const int* dst = ei + e;

    k_main<<<GRID, TPB>>>(src, dst, e, nodes, valid, edge_attr,
                          W1, b1, W2, b2, Wg, bg, Ww, bw, Wf, bf,
                          (float*)d_out);
}

// round 13
// speedup vs baseline: 1.1096x; 1.1096x over previous
#include <cuda_runtime.h>
#include <math.h>

// Problem constants: N=100000, L=48, E=1600000, ED=17, H=48
#define NN 100000
#define LL 48
#define EDD 17
#define EEMAX 1600000
#define CAP (1<<18)
#define NCAP (1<<16)
#define NBW 3136            // ceil(100000/32)=3125 padded to x4
#define GRID 148
#define TPB 1024
#define EPT 12              // 148*1024*12 = 1.82M >= E : single-shot scans
#define FULL 0xffffffffu

__device__ float g_x[NN*LL];
__device__ float g_v[NN*LL];
__device__ float g_agg[NN*LL];          // invariant: all-zero between runs
__device__ float g_wbase[EEMAX];
__device__ __align__(16) unsigned int g_flag1b[NBW];
__device__ __align__(16) unsigned int g_flag2b[NBW];
__device__ int g_list1[CAP];
__device__ int g_list2[CAP];
__device__ int g_list3[CAP];
__device__ int g_nlist1[NCAP];
__device__ int g_nlist2[NCAP];
__device__ int g_cnt[4];
__device__ int g_ncnt[4];
__device__ int g_bar[8];

__device__ __forceinline__ float geluf(float x) {
    return 0.5f * x * (1.0f + erff(x * 0.70710678118654752f));
}
__device__ __forceinline__ float sigm(float x) {
    return 1.0f / (1.0f + expf(-x));
}
__device__ __forceinline__ bool mark_bit(unsigned int* fw, int s) {
    unsigned int b = 1u << (s & 31);
    return (atomicOr(&fw[s >> 5], b) & b) == 0u;
}

// grid barrier (R6 form: atomicAdd poll)
__device__ __forceinline__ void gbar(int idx) {
    __syncthreads();
    if (threadIdx.x == 0) {
        __threadfence();
        atomicAdd(&g_bar[idx], 1);
        while (atomicAdd(&g_bar[idx], 0) < GRID) __nanosleep(64);
        __threadfence();
    }
    __syncthreads();
}
__device__ __forceinline__ void gbar_arrive(int idx) {
    __syncthreads();
    if (threadIdx.x == 0) {
        __threadfence();
        atomicAdd(&g_bar[idx], 1);
    }
}

// full-warp edge MLP: returns w_base on ALL lanes
__device__ __forceinline__ float edge_mlp(int eid, int lane, bool lo,
        const float* __restrict__ ea_all,
        const float* __restrict__ W1, const float* __restrict__ b1,
        const float* __restrict__ W2, const float* __restrict__ b2,
        const float* __restrict__ Wg, const float* __restrict__ bg,
        const float* __restrict__ Ww, float bw0) {
    const float* ea = ea_all + (long long)eid * EDD;

    float a  = b1[lane];
    float a2 = lo ? b1[lane + 32] : 0.f;
    #pragma unroll
    for (int k = 0; k < EDD; k++) {
        float ev = __ldg(&ea[k]);
        a = fmaf(ev, W1[k * 48 + lane], a);
        if (lo) a2 = fmaf(ev, W1[k * 48 + lane + 32], a2);
    }
    a = geluf(a); a2 = geluf(a2);

    float c  = b2[lane];
    float c2 = lo ? b2[lane + 32] : 0.f;
    #pragma unroll
    for (int k = 0; k < 48; k++) {
        float hk = (k < 32) ? __shfl_sync(FULL, a, k)
                            : __shfl_sync(FULL, a2, k - 32);
        c = fmaf(hk, W2[k * 48 + lane], c);
        if (lo) c2 = fmaf(hk, W2[k * 48 + lane + 32], c2);
    }
    c = fmaxf(c, 0.f); c2 = fmaxf(c2, 0.f);

    float d1 = bg[lane];
    float d2 = lo ? bg[lane + 32] : 0.f;
    #pragma unroll
    for (int k = 0; k < 48; k++) {
        float hk = (k < 32) ? __shfl_sync(FULL, c, k)
                            : __shfl_sync(FULL, c2, k - 32);
        d1 = fmaf(hk, Wg[k * 48 + lane], d1);
        if (lo) d2 = fmaf(hk, Wg[k * 48 + lane + 32], d2);
    }
    d1 = geluf(d1); d2 = geluf(d2);

    float p = d1 * Ww[lane] + (lo ? d2 * Ww[lane + 32] : 0.f);
    #pragma unroll
    for (int off = 16; off; off >>= 1) p += __shfl_xor_sync(FULL, p, off);
    return p + bw0;
}

// ---------------------------------------------------------------------------
// Reset: barriers, counters, flag bits (seed node 0)
// ---------------------------------------------------------------------------
__global__ void k_reset() {
    int i = blockIdx.x * blockDim.x + threadIdx.x;
    if (i < NBW) {
        unsigned int seed = (i == 0) ? 1u : 0u;
        g_flag1b[i] = seed;
        g_flag2b[i] = seed;
    }
    if (i == 0) {
        g_cnt[1] = g_cnt[2] = g_cnt[3] = 0;
        g_ncnt[1] = 1; g_ncnt[2] = 1;
        g_nlist1[0] = 0; g_nlist2[0] = 0;
        #pragma unroll
        for (int k = 0; k < 8; k++) g_bar[k] = 0;
    }
}

// ---------------------------------------------------------------------------
// Persistent kernel: single-shot EPT=12 scans, grid barriers between phases
// ---------------------------------------------------------------------------
__global__ void __launch_bounds__(TPB)
k_main(const int* __restrict__ src, const int* __restrict__ dst, int e,
       const float* __restrict__ nodes, const float* __restrict__ valid,
       const float* __restrict__ ea_all,
       const float* __restrict__ W1, const float* __restrict__ b1,
       const float* __restrict__ W2, const float* __restrict__ b2,
       const float* __restrict__ Wg, const float* __restrict__ bg,
       const float* __restrict__ Ww, const float* __restrict__ bw,
       const float* __restrict__ Wf, const float* __restrict__ bf,
       float* __restrict__ out) {
    __shared__ __align__(16) unsigned int sflag[NBW];
    const int tid  = threadIdx.x;
    const int lane = tid & 31;
    const bool lo  = (lane < 16);
    const int gtid = blockIdx.x * TPB + tid;
    const int gthreads = GRID * TPB;
    const int base = gtid * EPT;

    // ---------------- Phase 1: scan3 (dst==0), single shot ----------------
    {
        int d[EPT];
        #pragma unroll
        for (int t = 0; t < EPT; t++) d[t] = -1;
        if (base < e) {
            if (base + EPT <= e) {
                int4 a0 = __ldg((const int4*)(dst + base));
                int4 a1 = __ldg((const int4*)(dst + base + 4));
                int4 a2 = __ldg((const int4*)(dst + base + 8));
                d[0]=a0.x; d[1]=a0.y; d[2]=a0.z;  d[3]=a0.w;
                d[4]=a1.x; d[5]=a1.y; d[6]=a1.z;  d[7]=a1.w;
                d[8]=a2.x; d[9]=a2.y; d[10]=a2.z; d[11]=a2.w;
            } else {
                #pragma unroll
                for (int t = 0; t < EPT; t++) if (base + t < e) d[t] = dst[base + t];
            }
        }
        int mymask = 0;
        #pragma unroll
        for (int t = 0; t < EPT; t++) if (d[t] == 0) mymask |= 1 << t;
        if (__ballot_sync(FULL, mymask != 0)) {
            #pragma unroll 1
            for (int t = 0; t < EPT; t++) {
                bool pred = (mymask >> t) & 1;
                unsigned int m = __ballot_sync(FULL, pred);
                if (!m) continue;
                int leader = __ffs(m) - 1;
                int pos0 = 0;
                if (lane == leader) pos0 = atomicAdd(&g_cnt[3], __popc(m));
                pos0 = __shfl_sync(FULL, pos0, leader);
                if (pred) {
                    int p = pos0 + __popc(m & ((1u << lane) - 1));
                    int i = base + t;
                    if (p < CAP) g_list3[p] = i;
                    int s = __ldg(&src[i]);
                    if (mark_bit(g_flag2b, s)) {
                        int q = atomicAdd(&g_ncnt[2], 1);
                        if (q < NCAP) g_nlist2[q] = s;
                    }
                    if (mark_bit(g_flag1b, s)) {
                        int q = atomicAdd(&g_ncnt[1], 1);
                        if (q < NCAP) g_nlist1[q] = s;
                    }
                }
            }
        }
    }
    gbar(0);

    // ---------------- Phase 2: stage flag2, scan2 (single shot) ----------------
    {
        const uint4* gs = (const uint4*)g_flag2b;
        uint4* sd = (uint4*)sflag;
        for (int i = tid; i < NBW / 4; i += TPB) sd[i] = gs[i];
    }
    __syncthreads();
    {
        int d[EPT];
        #pragma unroll
        for (int t = 0; t < EPT; t++) d[t] = -1;
        if (base < e) {
            if (base + EPT <= e) {
                int4 a0 = __ldg((const int4*)(dst + base));      // L1-hot after P1
                int4 a1 = __ldg((const int4*)(dst + base + 4));
                int4 a2 = __ldg((const int4*)(dst + base + 8));
                d[0]=a0.x; d[1]=a0.y; d[2]=a0.z;  d[3]=a0.w;
                d[4]=a1.x; d[5]=a1.y; d[6]=a1.z;  d[7]=a1.w;
                d[8]=a2.x; d[9]=a2.y; d[10]=a2.z; d[11]=a2.w;
            } else {
                #pragma unroll
                for (int t = 0; t < EPT; t++) if (base + t < e) d[t] = dst[base + t];
            }
        }
        int mymask = 0;
        #pragma unroll
        for (int t = 0; t < EPT; t++)
            if (d[t] >= 0 && ((sflag[d[t] >> 5] >> (d[t] & 31)) & 1u)) mymask |= 1 << t;
        if (__ballot_sync(FULL, mymask != 0)) {
            #pragma unroll 1
            for (int t = 0; t < EPT; t++) {
                bool pred = (mymask >> t) & 1;
                unsigned int m = __ballot_sync(FULL, pred);
                if (!m) continue;
                int leader = __ffs(m) - 1;
                int pos0 = 0;
                if (lane == leader) pos0 = atomicAdd(&g_cnt[2], __popc(m));
                pos0 = __shfl_sync(FULL, pos0, leader);
                if (pred) {
                    int p = pos0 + __popc(m & ((1u << lane) - 1));
                    int i = base + t;
                    if (p < CAP) g_list2[p] = i;
                    int s = __ldg(&src[i]);
                    if (mark_bit(g_flag1b, s)) {
                        int q = atomicAdd(&g_ncnt[1], 1);
                        if (q < NCAP) g_nlist1[q] = s;
                    }
                }
            }
        }
    }
    gbar(1);

    // ---------------- Phase 3: stage flag1, scan1 -> list1 (single shot) -------
    {
        const uint4* gs = (const uint4*)g_flag1b;
        uint4* sd = (uint4*)sflag;
        for (int i = tid; i < NBW / 4; i += TPB) sd[i] = gs[i];
    }
    __syncthreads();
    {
        int d[EPT];
        #pragma unroll
        for (int t = 0; t < EPT; t++) d[t] = -1;
        if (base < e) {
            if (base + EPT <= e) {
                int4 a0 = __ldg((const int4*)(dst + base));
                int4 a1 = __ldg((const int4*)(dst + base + 4));
                int4 a2 = __ldg((const int4*)(dst + base + 8));
                d[0]=a0.x; d[1]=a0.y; d[2]=a0.z;  d[3]=a0.w;
                d[4]=a1.x; d[5]=a1.y; d[6]=a1.z;  d[7]=a1.w;
                d[8]=a2.x; d[9]=a2.y; d[10]=a2.z; d[11]=a2.w;
            } else {
                #pragma unroll
                for (int t = 0; t < EPT; t++) if (base + t < e) d[t] = dst[base + t];
            }
        }
        int mymask = 0;
        #pragma unroll
        for (int t = 0; t < EPT; t++)
            if (d[t] >= 0 && ((sflag[d[t] >> 5] >> (d[t] & 31)) & 1u)) mymask |= 1 << t;
        if (__ballot_sync(FULL, mymask != 0)) {
            #pragma unroll 1
            for (int t = 0; t < EPT; t++) {
                bool pred = (mymask >> t) & 1;
                unsigned int m = __ballot_sync(FULL, pred);
                if (!m) continue;
                int leader = __ffs(m) - 1;
                int pos0 = 0;
                if (lane == leader) pos0 = atomicAdd(&g_cnt[1], __popc(m));
                pos0 = __shfl_sync(FULL, pos0, leader);
                if (pred) {
                    int p = pos0 + __popc(m & ((1u << lane) - 1));
                    if (p < CAP) g_list1[p] = base + t;
                }
            }
        }
    }
    gbar(2);

    // ---------------- Phase 4: balanced wbase + agg1 over list1 ----------------
    {
        int gwarp = gtid >> 5;
        int nwarp = gthreads >> 5;
        int cnt = min(g_cnt[1], CAP);
        float bw0 = __ldg(bw);

        for (int it = gwarp; it < cnt; it += nwarp) {
            int eid = g_list1[it];
            float wb = edge_mlp(eid, lane, lo, ea_all, W1, b1, W2, b2,
                                Wg, bg, Ww, bw0);
            if (lane == 0) g_wbase[eid] = wb;

            int s = __ldg(&src[eid]);
            int dn = __ldg(&dst[eid]);
            long long sb = (long long)s * LL;
            float v0 = __ldg(&valid[sb + lane]);
            float v1 = lo ? __ldg(&valid[sb + lane + 32]) : 0.f;
            float x0 = __ldg(&nodes[sb + lane]) * v0;
            float x1 = lo ? __ldg(&nodes[sb + lane + 32]) * v1 : 0.f;
            float sv = v0 + v1;
            #pragma unroll
            for (int off = 16; off; off >>= 1) sv += __shfl_xor_sync(FULL, sv, off);
            float sg = sigm((sv * (1.0f / 48.0f)) * wb);
            float* ad = g_agg + (long long)dn * LL;
            atomicAdd(&ad[lane], x0 * sg);
            if (lo) atomicAdd(&ad[lane + 32], x1 * sg);
        }
    }
    gbar(3);

    // ---------------- Phase 5: grid-wide upd1 over nlist1 (restores agg=0) -----
    {
        float wf0 = __ldg(&Wf[0]), wf1 = __ldg(&Wf[1]), wf2 = __ldg(&Wf[2]);
        float b0 = __ldg(bf);
        int total = min(g_ncnt[1], NCAP) * LL;
        for (int q = gtid; q < total; q += gthreads) {
            int u = g_nlist1[q / LL];
            int l = q % LL;
            long long i = (long long)u * LL + l;
            float vo = __ldg(&valid[i]);
            float orig = __ldg(&nodes[i]) * vo;
            float xo = orig;
            float nh = __ldcg(&g_agg[i]);
            float nv = 1.0f - vo;
            float mm = sigm(nh * wf0 + xo * wf1 + nv * wf2 + b0);
            float xn = (1.0f - mm) * xo + nv * mm * nh;
            float vn = (l != 0 && (orig != xn || vo > 0.0f)) ? 1.0f : 0.0f;
            g_x[i] = xn;
            g_v[i] = vn;
            g_agg[i] = 0.f;
        }
    }
    gbar_arrive(4);
    if (blockIdx.x != 0) return;
    if (tid == 0) {
        while (atomicAdd(&g_bar[4], 0) < GRID) __nanosleep(64);
        __threadfence();
    }
    __syncthreads();

    // ---------------- Block 0: tail levels 2 and 3 ----------------
    float wf0 = __ldg(&Wf[0]), wf1 = __ldg(&Wf[1]), wf2 = __ldg(&Wf[2]);
    float b0 = __ldg(bf);

    #pragma unroll 1
    for (int level = 2; level <= 3; level++) {
        const int* list = (level == 2) ? g_list2 : g_list3;
        int cnt = min(g_cnt[level], CAP);
        int warp = tid >> 5;
        for (int it = warp; it < cnt; it += (TPB >> 5)) {
            int eid = list[it];
            int s = __ldg(&src[eid]);
            int dn = __ldg(&dst[eid]);
            long long sb = (long long)s * LL;
            float v0 = g_v[sb + lane];
            float v1 = lo ? g_v[sb + lane + 32] : 0.f;
            float x0 = g_x[sb + lane];
            float x1 = lo ? g_x[sb + lane + 32] : 0.f;
            float sv = v0 + v1;
            #pragma unroll
            for (int off = 16; off; off >>= 1) sv += __shfl_xor_sync(FULL, sv, off);
            float sg = sigm((sv * (1.0f / 48.0f)) * __ldcg(&g_wbase[eid]));
            float* ad = g_agg + (long long)dn * LL;
            atomicAdd(&ad[lane], x0 * sg);
            if (lo) atomicAdd(&ad[lane + 32], x1 * sg);
        }
        __syncthreads();

        int ncnt = (level == 2) ? min(g_ncnt[2], NCAP) : 1;
        int total = ncnt * LL;
        for (int q = tid; q < total; q += TPB) {
            int u = (level == 2) ? g_nlist2[q / LL] : 0;
            int l = q % LL;
            long long i = (long long)u * LL + l;
            float vv = __ldg(&valid[i]);
            float orig = __ldg(&nodes[i]) * vv;
            float xo = g_x[i];
            float vo = g_v[i];
            float nh = __ldcg(&g_agg[i]);
            float nv = 1.0f - vo;
            float mm = sigm(nh * wf0 + xo * wf1 + nv * wf2 + b0);
            float xn = (1.0f - mm) * xo + nv * mm * nh;
            float vn = (l != 0 && (orig != xn || vo > 0.0f)) ? 1.0f : 0.0f;
            g_x[i] = xn;
            g_v[i] = vn;
            g_agg[i] = 0.f;
            if (level == 3) out[l] = xn;
        }
        __syncthreads();
    }
}

extern "C" void kernel_launch(void* const* d_in, const int* in_sizes, int n_in,
                              void* d_out, int out_size) {
    const float* nodes     = (const float*)d_in[0];
    const int*   ei        = (const int*)d_in[1];
    const float* edge_attr = (const float*)d_in[2];
    const float* valid     = (const float*)d_in[3];
    const float* W1 = (const float*)d_in[6];
    const float* b1 = (const float*)d_in[7];
    const float* W2 = (const float*)d_in[8];
    const float* b2 = (const float*)d_in[9];
    const float* Wg = (const float*)d_in[10];
    const float* bg = (const float*)d_in[11];
    const float* Ww = (const float*)d_in[12];
    const float* bw = (const float*)d_in[13];
    const float* Wf = (const float*)d_in[14];
    const float* bf = (const float*)d_in[15];

    int e = in_sizes[1] / 2;
    const int* src = ei;
    const int* dst = ei + e;

    k_reset<<<(NBW + 511) / 512, 512>>>();
    k_main<<<GRID, TPB>>>(src, dst, e, nodes, valid, edge_attr,
                          W1, b1, W2, b2, Wg, bg, Ww, bw, Wf, bf,
                          (float*)d_out);
}

// round 14
// speedup vs baseline: 1.2143x; 1.0944x over previous
#include <cuda_runtime.h>
#include <math.h>

// Problem constants: N=100000, L=48, E=1600000, ED=17, H=48
#define NN 100000
#define LL 48
#define EDD 17
#define EEMAX 1600000
#define CAP (1<<18)
#define NCAP (1<<16)
#define NBW 3136            // ceil(100000/32)=3125 padded to x4
#define GRID 148
#define TPB 1024
#define EPT 12              // 148*1024*12 = 1.82M >= E : single-shot scans
#define FULL 0xffffffffu

__device__ float g_x[NN*LL];
__device__ float g_v[NN*LL];
__device__ float g_agg[NN*LL];          // invariant: all-zero between runs
__device__ float g_wbase[EEMAX];
__device__ __align__(16) unsigned int g_flag1b[NBW];
__device__ __align__(16) unsigned int g_flag2b[NBW];
__device__ int g_list1[CAP];
__device__ int g_list2[CAP];
__device__ int g_list3[CAP];
__device__ int g_nlist1[NCAP];
__device__ int g_nlist2[NCAP];
__device__ int g_cnt[4];
__device__ int g_ncnt[4];
__device__ int g_bar[8];

__device__ __forceinline__ float geluf(float x) {
    return 0.5f * x * (1.0f + erff(x * 0.70710678118654752f));
}
__device__ __forceinline__ float sigm(float x) {
    return 1.0f / (1.0f + expf(-x));
}
__device__ __forceinline__ bool mark_bit(unsigned int* fw, int s) {
    unsigned int b = 1u << (s & 31);
    return (atomicOr(&fw[s >> 5], b) & b) == 0u;
}

// grid barrier: arrival = atomic RMW; poll = volatile plain load
__device__ __forceinline__ void gbar(int idx) {
    __syncthreads();
    if (threadIdx.x == 0) {
        __threadfence();
        atomicAdd(&g_bar[idx], 1);
        while (*(volatile int*)&g_bar[idx] < GRID) __nanosleep(64);
        __threadfence();
    }
    __syncthreads();
}
__device__ __forceinline__ void gbar_arrive(int idx) {
    __syncthreads();
    if (threadIdx.x == 0) {
        __threadfence();
        atomicAdd(&g_bar[idx], 1);
    }
}

// warp exclusive scan of per-lane hit counts; returns {excl offset, total}
__device__ __forceinline__ void warp_scan(int nh, int lane, int& excl, int& total) {
    int pre = nh;
    #pragma unroll
    for (int off = 1; off < 32; off <<= 1) {
        int v = __shfl_up_sync(FULL, pre, off);
        if (lane >= off) pre += v;
    }
    total = __shfl_sync(FULL, pre, 31);
    excl = pre - nh;
}

// full-warp edge MLP: returns w_base on ALL lanes
__device__ __forceinline__ float edge_mlp(int eid, int lane, bool lo,
        const float* __restrict__ ea_all,
        const float* __restrict__ W1, const float* __restrict__ b1,
        const float* __restrict__ W2, const float* __restrict__ b2,
        const float* __restrict__ Wg, const float* __restrict__ bg,
        const float* __restrict__ Ww, float bw0) {
    const float* ea = ea_all + (long long)eid * EDD;

    float a  = b1[lane];
    float a2 = lo ? b1[lane + 32] : 0.f;
    #pragma unroll
    for (int k = 0; k < EDD; k++) {
        float ev = __ldg(&ea[k]);
        a = fmaf(ev, W1[k * 48 + lane], a);
        if (lo) a2 = fmaf(ev, W1[k * 48 + lane + 32], a2);
    }
    a = geluf(a); a2 = geluf(a2);

    float c  = b2[lane];
    float c2 = lo ? b2[lane + 32] : 0.f;
    #pragma unroll
    for (int k = 0; k < 48; k++) {
        float hk = (k < 32) ? __shfl_sync(FULL, a, k)
                            : __shfl_sync(FULL, a2, k - 32);
        c = fmaf(hk, W2[k * 48 + lane], c);
        if (lo) c2 = fmaf(hk, W2[k * 48 + lane + 32], c2);
    }
    c = fmaxf(c, 0.f); c2 = fmaxf(c2, 0.f);

    float d1 = bg[lane];
    float d2 = lo ? bg[lane + 32] : 0.f;
    #pragma unroll
    for (int k = 0; k < 48; k++) {
        float hk = (k < 32) ? __shfl_sync(FULL, c, k)
                            : __shfl_sync(FULL, c2, k - 32);
        d1 = fmaf(hk, Wg[k * 48 + lane], d1);
        if (lo) d2 = fmaf(hk, Wg[k * 48 + lane + 32], d2);
    }
    d1 = geluf(d1); d2 = geluf(d2);

    float p = d1 * Ww[lane] + (lo ? d2 * Ww[lane + 32] : 0.f);
    #pragma unroll
    for (int off = 16; off; off >>= 1) p += __shfl_xor_sync(FULL, p, off);
    return p + bw0;
}

// ---------------------------------------------------------------------------
// Reset: barriers, counters, flag bits (seed node 0)
// ---------------------------------------------------------------------------
__global__ void k_reset() {
    int i = blockIdx.x * blockDim.x + threadIdx.x;
    if (i < NBW) {
        unsigned int seed = (i == 0) ? 1u : 0u;
        g_flag1b[i] = seed;
        g_flag2b[i] = seed;
    }
    if (i == 0) {
        g_cnt[1] = g_cnt[2] = g_cnt[3] = 0;
        g_ncnt[1] = 1; g_ncnt[2] = 1;
        g_nlist1[0] = 0; g_nlist2[0] = 0;
        #pragma unroll
        for (int k = 0; k < 8; k++) g_bar[k] = 0;
    }
}

// ---------------------------------------------------------------------------
// Persistent kernel: single-shot EPT=12 scans, warp-scan appends
// ---------------------------------------------------------------------------
__global__ void __launch_bounds__(TPB)
k_main(const int* __restrict__ src, const int* __restrict__ dst, int e,
       const float* __restrict__ nodes, const float* __restrict__ valid,
       const float* __restrict__ ea_all,
       const float* __restrict__ W1, const float* __restrict__ b1,
       const float* __restrict__ W2, const float* __restrict__ b2,
       const float* __restrict__ Wg, const float* __restrict__ bg,
       const float* __restrict__ Ww, const float* __restrict__ bw,
       const float* __restrict__ Wf, const float* __restrict__ bf,
       float* __restrict__ out) {
    __shared__ __align__(16) unsigned int sflag[NBW];
    const int tid  = threadIdx.x;
    const int lane = tid & 31;
    const bool lo  = (lane < 16);
    const int gtid = blockIdx.x * TPB + tid;
    const int gthreads = GRID * TPB;
    const int base = gtid * EPT;

    // ---------------- Phase 1: scan3 (dst==0), single shot ----------------
    {
        int d[EPT];
        #pragma unroll
        for (int t = 0; t < EPT; t++) d[t] = -1;
        if (base < e) {
            if (base + EPT <= e) {
                int4 a0 = __ldg((const int4*)(dst + base));
                int4 a1 = __ldg((const int4*)(dst + base + 4));
                int4 a2 = __ldg((const int4*)(dst + base + 8));
                d[0]=a0.x; d[1]=a0.y; d[2]=a0.z;  d[3]=a0.w;
                d[4]=a1.x; d[5]=a1.y; d[6]=a1.z;  d[7]=a1.w;
                d[8]=a2.x; d[9]=a2.y; d[10]=a2.z; d[11]=a2.w;
            } else {
                #pragma unroll
                for (int t = 0; t < EPT; t++) if (base + t < e) d[t] = dst[base + t];
            }
        }
        unsigned int mymask = 0;
        #pragma unroll
        for (int t = 0; t < EPT; t++) if (d[t] == 0) mymask |= 1u << t;

        int excl, total;
        warp_scan(__popc(mymask), lane, excl, total);
        if (total) {
            int pos0 = 0;
            if (lane == 31) pos0 = atomicAdd(&g_cnt[3], total);
            pos0 = __shfl_sync(FULL, pos0, 31);
            int p = pos0 + excl;
            unsigned int mm = mymask;
            while (mm) {
                int t = __ffs(mm) - 1; mm &= mm - 1;
                int i = base + t;
                if (p < CAP) g_list3[p] = i;
                p++;
                int s = __ldg(&src[i]);
                if (mark_bit(g_flag2b, s)) {
                    int q = atomicAdd(&g_ncnt[2], 1);
                    if (q < NCAP) g_nlist2[q] = s;
                }
                if (mark_bit(g_flag1b, s)) {
                    int q = atomicAdd(&g_ncnt[1], 1);
                    if (q < NCAP) g_nlist1[q] = s;
                }
            }
        }
    }
    gbar(0);

    // ---------------- Phase 2: stage flag2, scan2 (single shot) ----------------
    {
        const uint4* gs = (const uint4*)g_flag2b;
        uint4* sd = (uint4*)sflag;
        for (int i = tid; i < NBW / 4; i += TPB) sd[i] = gs[i];
    }
    __syncthreads();
    {
        int d[EPT];
        #pragma unroll
        for (int t = 0; t < EPT; t++) d[t] = -1;
        if (base < e) {
            if (base + EPT <= e) {
                int4 a0 = __ldg((const int4*)(dst + base));      // L1-hot after P1
                int4 a1 = __ldg((const int4*)(dst + base + 4));
                int4 a2 = __ldg((const int4*)(dst + base + 8));
                d[0]=a0.x; d[1]=a0.y; d[2]=a0.z;  d[3]=a0.w;
                d[4]=a1.x; d[5]=a1.y; d[6]=a1.z;  d[7]=a1.w;
                d[8]=a2.x; d[9]=a2.y; d[10]=a2.z; d[11]=a2.w;
            } else {
                #pragma unroll
                for (int t = 0; t < EPT; t++) if (base + t < e) d[t] = dst[base + t];
            }
        }
        unsigned int mymask = 0;
        #pragma unroll
        for (int t = 0; t < EPT; t++)
            if (d[t] >= 0 && ((sflag[d[t] >> 5] >> (d[t] & 31)) & 1u)) mymask |= 1u << t;

        int excl, total;
        warp_scan(__popc(mymask), lane, excl, total);
        if (total) {
            int pos0 = 0;
            if (lane == 31) pos0 = atomicAdd(&g_cnt[2], total);
            pos0 = __shfl_sync(FULL, pos0, 31);
            int p = pos0 + excl;
            unsigned int mm = mymask;
            while (mm) {
                int t = __ffs(mm) - 1; mm &= mm - 1;
                int i = base + t;
                if (p < CAP) g_list2[p] = i;
                p++;
                int s = __ldg(&src[i]);
                if (mark_bit(g_flag1b, s)) {
                    int q = atomicAdd(&g_ncnt[1], 1);
                    if (q < NCAP) g_nlist1[q] = s;
                }
            }
        }
    }
    gbar(1);

    // ---------------- Phase 3: stage flag1, scan1 -> list1 (single shot) -------
    {
        const uint4* gs = (const uint4*)g_flag1b;
        uint4* sd = (uint4*)sflag;
        for (int i = tid; i < NBW / 4; i += TPB) sd[i] = gs[i];
    }
    __syncthreads();
    {
        int d[EPT];
        #pragma unroll
        for (int t = 0; t < EPT; t++) d[t] = -1;
        if (base < e) {
            if (base + EPT <= e) {
                int4 a0 = __ldg((const int4*)(dst + base));
                int4 a1 = __ldg((const int4*)(dst + base + 4));
                int4 a2 = __ldg((const int4*)(dst + base + 8));
                d[0]=a0.x; d[1]=a0.y; d[2]=a0.z;  d[3]=a0.w;
                d[4]=a1.x; d[5]=a1.y; d[6]=a1.z;  d[7]=a1.w;
                d[8]=a2.x; d[9]=a2.y; d[10]=a2.z; d[11]=a2.w;
            } else {
                #pragma unroll
                for (int t = 0; t < EPT; t++) if (base + t < e) d[t] = dst[base + t];
            }
        }
        unsigned int mymask = 0;
        #pragma unroll
        for (int t = 0; t < EPT; t++)
            if (d[t] >= 0 && ((sflag[d[t] >> 5] >> (d[t] & 31)) & 1u)) mymask |= 1u << t;

        int excl, total;
        warp_scan(__popc(mymask), lane, excl, total);
        if (total) {
            int pos0 = 0;
            if (lane == 31) pos0 = atomicAdd(&g_cnt[1], total);
            pos0 = __shfl_sync(FULL, pos0, 31);
            int p = pos0 + excl;
            unsigned int mm = mymask;
            while (mm) {
                int t = __ffs(mm) - 1; mm &= mm - 1;
                if (p < CAP) g_list1[p] = base + t;
                p++;
            }
        }
    }
    gbar(2);

    // ---------------- Phase 4: balanced wbase + agg1 over list1 ----------------
    {
        int gwarp = gtid >> 5;
        int nwarp = gthreads >> 5;
        int cnt = min(g_cnt[1], CAP);
        float bw0 = __ldg(bw);

        for (int it = gwarp; it < cnt; it += nwarp) {
            int eid = g_list1[it];
            float wb = edge_mlp(eid, lane, lo, ea_all, W1, b1, W2, b2,
                                Wg, bg, Ww, bw0);
            if (lane == 0) g_wbase[eid] = wb;

            int s = __ldg(&src[eid]);
            int dn = __ldg(&dst[eid]);
            long long sb = (long long)s * LL;
            float v0 = __ldg(&valid[sb + lane]);
            float v1 = lo ? __ldg(&valid[sb + lane + 32]) : 0.f;
            float x0 = __ldg(&nodes[sb + lane]) * v0;
            float x1 = lo ? __ldg(&nodes[sb + lane + 32]) * v1 : 0.f;
            float sv = v0 + v1;
            #pragma unroll
            for (int off = 16; off; off >>= 1) sv += __shfl_xor_sync(FULL, sv, off);
            float sg = sigm((sv * (1.0f / 48.0f)) * wb);
            float* ad = g_agg + (long long)dn * LL;
            atomicAdd(&ad[lane], x0 * sg);
            if (lo) atomicAdd(&ad[lane + 32], x1 * sg);
        }
    }
    gbar(3);

    // ---------------- Phase 5: grid-wide upd1 over nlist1 (restores agg=0) -----
    {
        float wf0 = __ldg(&Wf[0]), wf1 = __ldg(&Wf[1]), wf2 = __ldg(&Wf[2]);
        float b0 = __ldg(bf);
        int total = min(g_ncnt[1], NCAP) * LL;
        for (int q = gtid; q < total; q += gthreads) {
            int u = g_nlist1[q / LL];
            int l = q % LL;
            long long i = (long long)u * LL + l;
            float vo = __ldg(&valid[i]);
            float orig = __ldg(&nodes[i]) * vo;
            float xo = orig;
            float nh = __ldcg(&g_agg[i]);
            float nv = 1.0f - vo;
            float mm = sigm(nh * wf0 + xo * wf1 + nv * wf2 + b0);
            float xn = (1.0f - mm) * xo + nv * mm * nh;
            float vn = (l != 0 && (orig != xn || vo > 0.0f)) ? 1.0f : 0.0f;
            g_x[i] = xn;
            g_v[i] = vn;
            g_agg[i] = 0.f;
        }
    }
    gbar_arrive(4);
    if (blockIdx.x != 0) return;
    if (tid == 0) {
        while (*(volatile int*)&g_bar[4] < GRID) __nanosleep(64);
        __threadfence();
    }
    __syncthreads();

    // ---------------- Block 0: tail levels 2 and 3 ----------------
    float wf0 = __ldg(&Wf[0]), wf1 = __ldg(&Wf[1]), wf2 = __ldg(&Wf[2]);
    float b0 = __ldg(bf);

    #pragma unroll 1
    for (int level = 2; level <= 3; level++) {
        const int* list = (level == 2) ? g_list2 : g_list3;
        int cnt = min(g_cnt[level], CAP);
        int warp = tid >> 5;
        for (int it = warp; it < cnt; it += (TPB >> 5)) {
            int eid = list[it];
            int s = __ldg(&src[eid]);
            int dn = __ldg(&dst[eid]);
            long long sb = (long long)s * LL;
            float v0 = g_v[sb + lane];
            float v1 = lo ? g_v[sb + lane + 32] : 0.f;
            float x0 = g_x[sb + lane];
            float x1 = lo ? g_x[sb + lane + 32] : 0.f;
            float sv = v0 + v1;
            #pragma unroll
            for (int off = 16; off; off >>= 1) sv += __shfl_xor_sync(FULL, sv, off);
            float sg = sigm((sv * (1.0f / 48.0f)) * __ldcg(&g_wbase[eid]));
            float* ad = g_agg + (long long)dn * LL;
            atomicAdd(&ad[lane], x0 * sg);
            if (lo) atomicAdd(&ad[lane + 32], x1 * sg);
        }
        __syncthreads();

        int ncnt = (level == 2) ? min(g_ncnt[2], NCAP) : 1;
        int total = ncnt * LL;
        for (int q = tid; q < total; q += TPB) {
            int u = (level == 2) ? g_nlist2[q / LL] : 0;
            int l = q % LL;
            long long i = (long long)u * LL + l;
            float vv = __ldg(&valid[i]);
            float orig = __ldg(&nodes[i]) * vv;
            float xo = g_x[i];
            float vo = g_v[i];
            float nh = __ldcg(&g_agg[i]);
            float nv = 1.0f - vo;
            float mm = sigm(nh * wf0 + xo * wf1 + nv * wf2 + b0);
            float xn = (1.0f - mm) * xo + nv * mm * nh;
            float vn = (l != 0 && (orig != xn || vo > 0.0f)) ? 1.0f : 0.0f;
            g_x[i] = xn;
            g_v[i] = vn;
            g_agg[i] = 0.f;
            if (level == 3) out[l] = xn;
        }
        __syncthreads();
    }
}

extern "C" void kernel_launch(void* const* d_in, const int* in_sizes, int n_in,
                              void* d_out, int out_size) {
    const float* nodes     = (const float*)d_in[0];
    const int*   ei        = (const int*)d_in[1];
    const float* edge_attr = (const float*)d_in[2];
    const float* valid     = (const float*)d_in[3];
    const float* W1 = (const float*)d_in[6];
    const float* b1 = (const float*)d_in[7];
    const float* W2 = (const float*)d_in[8];
    const float* b2 = (const float*)d_in[9];
    const float* Wg = (const float*)d_in[10];
    const float* bg = (const float*)d_in[11];
    const float* Ww = (const float*)d_in[12];
    const float* bw = (const float*)d_in[13];
    const float* Wf = (const float*)d_in[14];
    const float* bf = (const float*)d_in[15];

    int e = in_sizes[1] / 2;
    const int* src = ei;
    const int* dst = ei + e;

    k_reset<<<(NBW + 511) / 512, 512>>>();
    k_main<<<GRID, TPB>>>(src, dst, e, nodes, valid, edge_attr,
                          W1, b1, W2, b2, Wg, bg, Ww, bw, Wf, bf,
                          (float*)d_out);
}